// round 7
// baseline (speedup 1.0000x reference)
#include <cuda_runtime.h>

#define B 16
#define NA 65536
#define NG 32
#define IOU_BLKS 64      // per image: 64 blocks x 256 threads x 4 anchors
#define CAP 16384

// ---------------- scratch (device globals; zero at module load) ----------------
__device__ unsigned long long g_spart[B * IOU_BLKS * NG];
__device__ float        g_neg[B * NA];
__device__ unsigned int g_hcnt[B * 2048];   // k_main atomics; k_tail consumes + re-zeroes
__device__ int   g_np[B];
__device__ float g_loc[B];
__device__ float g_pos[B];
__device__ float g_cf[B];
__device__ float g_locf[B];
__device__ int   g_npf[B];
__device__ unsigned g_done;

__device__ __forceinline__ float sl1(float x) {
    float ax = fabsf(x);
    return ax < 1.f ? 0.5f * ax * ax : ax - 0.5f;
}

// ---------------- K1: IoU + per-anchor loss + count hist ----------------
__global__ __launch_bounds__(256) void k_main(const float4* __restrict__ bbox,
                                              const float* __restrict__ conf,
                                              const float4* __restrict__ anchors,
                                              const float4* __restrict__ gt) {
    __shared__ float4 sgt[NG];
    __shared__ float sarea[NG];
    __shared__ unsigned long long sp[8][NG];
    __shared__ unsigned int shist[2048];
    __shared__ int s_np; __shared__ float s_loc, s_pos;

    int tid = threadIdx.x, lane = tid & 31, wid = tid >> 5;
    int b = blockIdx.x >> 6, blk = blockIdx.x & 63;
    int abase = blk * 1024 + tid * 4;

    for (int i = tid; i < 2048; i += 256) shist[i] = 0;
    if (tid < NG) {
        float4 g = gt[b * NG + tid];
        sgt[tid] = g;
        sarea[tid] = (g.z - g.x) * (g.w - g.y);
    }
    if (tid == 0) { s_np = 0; s_loc = 0.f; s_pos = 0.f; }
    __syncthreads();

    float4 an[4]; float ar[4], best[4]; int bg[4];
    const float4* ap = anchors + b * NA + abase;
#pragma unroll
    for (int j = 0; j < 4; j++) {
        an[j] = ap[j];
        ar[j] = (an[j].z - an[j].x) * (an[j].w - an[j].y);
        best[j] = -1.f; bg[j] = 0;
    }

#pragma unroll 2
    for (int g = 0; g < NG; g++) {
        float4 gb = sgt[g];
        float sa = sarea[g];
        float gmax = -1.f; int gidx = 0;
#pragma unroll
        for (int j = 0; j < 4; j++) {
            float lx = fmaxf(an[j].x, gb.x), ly = fmaxf(an[j].y, gb.y);
            float rx = fminf(an[j].z, gb.z), ry = fminf(an[j].w, gb.w);
            float w = fmaxf(rx - lx, 0.f), h = fmaxf(ry - ly, 0.f);
            float inter = w * h;
            float q = __fdividef(inter, (ar[j] + sa) - inter);
            if (q > best[j]) { best[j] = q; bg[j] = g; }   // first max = lowest g
            if (q > gmax) { gmax = q; gidx = j; }          // first max = lowest anchor
        }
        unsigned bits = __float_as_uint(gmax);
        unsigned m = __reduce_max_sync(0xffffffffu, bits);
        unsigned ball = __ballot_sync(0xffffffffu, bits == m);
        if (lane == (__ffs(ball) - 1))
            sp[wid][g] = ((unsigned long long)m << 32) | (unsigned)(~(abase + gidx));
    }

    float4 cf4 = *(const float4*)(conf + b * NA + abase);
    float pv[4] = {cf4.x, cf4.y, cf4.z, cf4.w};
    float ng[4];
    int npl = 0; float locl = 0.f, posl = 0.f;
#pragma unroll
    for (int j = 0; j < 4; j++) {
        if (best[j] > 0.5f) {
            ng[j] = 0.f;
            posl += -__logf(pv[j]);
            float4 bp = bbox[b * NA + abase + j];
            float4 m = sgt[bg[j]];
            float d0 = (bp.x + bp.z) * 0.5f - (m.x + m.z) * 0.5f;
            float d1 = (bp.y + bp.w) * 0.5f - (m.y + m.w) * 0.5f;
            float d2 = (bp.z - bp.x) - (m.z - m.x);
            float d3 = (bp.w - bp.y) - (m.w - m.y);
            locl += sl1(d0) + sl1(d1) + sl1(d2) + sl1(d3);
            npl++;
        } else {
            ng[j] = fmaxf(-__logf(1.0f - pv[j]), 0.0f);
        }
        atomicAdd(&shist[__float_as_uint(ng[j]) >> 21], 1u);
    }
    *(float4*)(g_neg + b * NA + abase) = make_float4(ng[0], ng[1], ng[2], ng[3]);
    if (npl) { atomicAdd(&s_np, npl); atomicAdd(&s_loc, locl); atomicAdd(&s_pos, posl); }
    __syncthreads();

    for (int i = tid; i < 2048; i += 256) {
        unsigned c = shist[i];
        if (c) atomicAdd(&g_hcnt[b * 2048 + i], c);
    }
    if (tid < NG) {
        unsigned long long m = sp[0][tid];
#pragma unroll
        for (int w = 1; w < 8; w++) { unsigned long long v = sp[w][tid]; if (v > m) m = v; }
        g_spart[(b * IOU_BLKS + blk) * NG + tid] = m;
    }
    if (tid == 0 && s_np) {
        atomicAdd(&g_np[b], s_np);
        atomicAdd(&g_loc[b], s_loc);
        atomicAdd(&g_pos[b], s_pos);
    }
}

// ---------------- K2: corrections + select + scan + warp-radix + final ----------------
__device__ double blockReduceD(double v, double* sred) {
    __syncthreads();
#pragma unroll
    for (int o = 16; o; o >>= 1) v += __shfl_down_sync(0xffffffffu, v, o);
    int w = threadIdx.x >> 5, l = threadIdx.x & 31;
    if (l == 0) sred[w] = v;
    __syncthreads();
    if (threadIdx.x < 32) {
        v = sred[threadIdx.x];
#pragma unroll
        for (int o = 16; o; o >>= 1) v += __shfl_down_sync(0xffffffffu, v, o);
    }
    return v;   // valid on tid 0
}

extern __shared__ float dbuf[];   // 2*CAP floats (ping-pong)

__global__ __launch_bounds__(1024) void k_tail(const float4* __restrict__ bbox,
                                               const float* __restrict__ conf,
                                               const float4* __restrict__ anchors,
                                               const float4* __restrict__ gt,
                                               float* __restrict__ out) {
    __shared__ float4 sgt[NG];
    __shared__ float sarea[NG];
    __shared__ unsigned scnt[2048];
    __shared__ unsigned long long s_gmax[NG];
    __shared__ int s_af[NG];
    __shared__ unsigned h128[128];
    __shared__ float s128f[128];
    __shared__ int s_n, s_sel;
    __shared__ unsigned s_kk;
    __shared__ double sred[32];
    __shared__ double s_acc;
    __shared__ int s_npc; __shared__ float s_locc, s_posc;

    int b = blockIdx.x, tid = threadIdx.x;
    int lane = tid & 31, wrp = tid >> 5;

    // ---- Phase A: setup, corrections, bin select ----
    if (tid < NG) {
        float4 g = gt[b * NG + tid];
        sgt[tid] = g;
        sarea[tid] = (g.z - g.x) * (g.w - g.y);
        s_gmax[tid] = 0ull;
    }
    if (tid == 0) { s_npc = 0; s_locc = 0.f; s_posc = 0.f; s_sel = 0; s_kk = 1; s_n = 0; }
    scnt[tid]        = g_hcnt[b * 2048 + tid];
    scnt[tid + 1024] = g_hcnt[b * 2048 + tid + 1024];
    g_hcnt[b * 2048 + tid] = 0;
    g_hcnt[b * 2048 + tid + 1024] = 0;
    __syncthreads();

    {
        unsigned long long v0 = g_spart[(size_t)b * 2048 + tid];
        unsigned long long v1 = g_spart[(size_t)b * 2048 + tid + 1024];
        atomicMax(&s_gmax[tid & 31], v0);
        atomicMax(&s_gmax[(tid + 1024) & 31], v1);
    }
    __syncthreads();
    if (tid < NG) s_af[tid] = (int)(~(unsigned)(s_gmax[tid] & 0xffffffffull));
    __syncthreads();

    {   // warp wrp handles forced anchor of gt wrp; 32 lanes = 32 gts in parallel
        int af = s_af[wrp];
        unsigned dup = __ballot_sync(0xffffffffu, lane < wrp && s_af[lane] == af);
        if (dup == 0) {
            float4 an = anchors[b * NA + af];
            float area_a = (an.z - an.x) * (an.w - an.y);
            float4 gb = sgt[lane];
            float lx = fmaxf(an.x, gb.x), ly = fmaxf(an.y, gb.y);
            float rx = fminf(an.z, gb.z), ry = fminf(an.w, gb.w);
            float w = fmaxf(rx - lx, 0.f), h = fmaxf(ry - ly, 0.f);
            float inter = w * h;
            float q = __fdividef(inter, (area_a + sarea[lane]) - inter);  // bit-identical to K1
            unsigned bits = __float_as_uint(q);
            unsigned m = __reduce_max_sync(0xffffffffu, bits);
            unsigned ball = __ballot_sync(0xffffffffu, bits == m);
            int bgi = __ffs(ball) - 1;
            float bestq = __uint_as_float(m);
            if (!(bestq > 0.5f) && lane == 0) {
                int idx = b * NA + af;
                float old = g_neg[idx];
                g_neg[idx] = 0.f;
                atomicSub(&scnt[__float_as_uint(old) >> 21], 1u);
                atomicAdd(&scnt[0], 1u);
                float p = conf[idx];
                float4 bp = bbox[idx];
                float4 mg = sgt[bgi];
                float d0 = (bp.x + bp.z) * 0.5f - (mg.x + mg.z) * 0.5f;
                float d1 = (bp.y + bp.w) * 0.5f - (mg.y + mg.w) * 0.5f;
                float d2 = (bp.z - bp.x) - (mg.z - mg.x);
                float d3 = (bp.w - bp.y) - (mg.w - mg.y);
                atomicAdd(&s_npc, 1);
                atomicAdd(&s_locc, sl1(d0) + sl1(d1) + sl1(d2) + sl1(d3));
                atomicAdd(&s_posc, -__logf(p));
            }
        }
    }
    __syncthreads();

    int np = g_np[b] + s_npc;
    float posn = (g_pos[b] + s_posc) / (float)max(np, 1);
    float locim = g_loc[b] + s_locc;
    int kn = min(3 * np, NA - np);
    if (tid == 0) { g_np[b] = 0; g_loc[b] = 0.f; g_pos[b] = 0.f; }

    // suffix-inclusive scan of 2048 counts
    for (int off = 1; off < 2048; off <<= 1) {
        unsigned a0 = (tid + off < 2048) ? scnt[tid + off] : 0u;
        unsigned a1 = (tid + 1024 + off < 2048) ? scnt[tid + 1024 + off] : 0u;
        __syncthreads();
        scnt[tid] += a0; scnt[tid + 1024] += a1;
        __syncthreads();
    }
    unsigned kk0 = (unsigned)max(kn, 1);
    {
        unsigned incl0 = scnt[tid], excl0 = scnt[tid + 1];
        if (excl0 < kk0 && kk0 <= incl0) { s_sel = tid; s_kk = kk0 - excl0; }
        int i1 = tid + 1024;
        unsigned incl1 = scnt[i1], excl1 = (i1 < 2047) ? scnt[i1 + 1] : 0u;
        if (excl1 < kk0 && kk0 <= incl1) { s_sel = i1; s_kk = kk0 - excl1; }
    }
    __syncthreads();
    int sel = s_sel;

    double negacc = 0.0;
    if (kn > 0) {
        // ---- Phase B: one unrolled pass, plain adds + plain atomic compaction ----
        const float4* neg4 = (const float4*)(g_neg + b * NA);
        float acc = 0.f;
#pragma unroll
        for (int ii = 0; ii < 16; ii++) {
            float4 v = neg4[tid + ii * 1024];
            float vv[4] = {v.x, v.y, v.z, v.w};
#pragma unroll
            for (int c = 0; c < 4; c++) {
                int key = (int)(__float_as_uint(vv[c]) >> 21);
                if (key > sel) acc += vv[c];
                else if (key == sel) {
                    int p = atomicAdd(&s_n, 1);
                    if (p < CAP) dbuf[p] = vv[c];
                }
            }
        }
        double r = blockReduceD((double)acc, sred);
        if (tid == 0) s_acc = r;
        __syncthreads();

        // ---- Phase C: warp 0 only, no block barriers ----
        if (wrp == 0) {
            int cn = s_n;
            unsigned kk = s_kk;
            bool ovf = cn > CAP;
            int curn = ovf ? 0 : cn;
            float* cur = dbuf; float* nxt = dbuf + CAP;
            unsigned pref = (unsigned)sel;
            double lacc = 0.0;                   // per-lane partial of included sums

#pragma unroll 1
            for (int shift = 14; shift >= 0; shift -= 7) {
                if (!ovf && kk == (unsigned)curn) {       // take-all fast path
                    float as = 0.f;
                    for (int i = lane; i < curn; i += 32) as += cur[i];
                    lacc += (double)as;
                    kk = 0;
                    break;
                }
                // zero bins
#pragma unroll
                for (int j = 0; j < 4; j++) { h128[lane + 32 * j] = 0u; s128f[lane + 32 * j] = 0.f; }
                __syncwarp();
                if (!ovf) {
                    for (int i = lane; i < curn; i += 32) {
                        float v = cur[i];
                        unsigned key = (__float_as_uint(v) >> shift) & 127u;
                        atomicAdd(&h128[key], 1u);
                        atomicAdd(&s128f[key], v);
                    }
                } else {   // never expected: global rescan by one warp
                    const float* negp = g_neg + b * NA;
                    for (int i = lane; i < NA; i += 32) {
                        float v = negp[i];
                        unsigned bits = __float_as_uint(v);
                        if ((bits >> (shift + 7)) == pref) {
                            atomicAdd(&h128[(bits >> shift) & 127u], 1u);
                            atomicAdd(&s128f[(bits >> shift) & 127u], v);
                        }
                    }
                }
                __syncwarp();
                // suffix-inclusive scan, 4 bins per lane
                for (int off = 1; off < 128; off <<= 1) {
                    unsigned a[4];
#pragma unroll
                    for (int j = 0; j < 4; j++) {
                        int idx = lane + 32 * j;
                        a[j] = (idx + off < 128) ? h128[idx + off] : 0u;
                    }
                    __syncwarp();
#pragma unroll
                    for (int j = 0; j < 4; j++) h128[lane + 32 * j] += a[j];
                    __syncwarp();
                }
#pragma unroll
                for (int j = 0; j < 4; j++) {
                    int idx = lane + 32 * j;
                    unsigned incl = h128[idx], excl = (idx < 127) ? h128[idx + 1] : 0u;
                    if (excl < kk && kk <= incl) { s_sel = idx; s_kk = kk - excl; }
                }
                if (lane == 0) s_n = 0;
                __syncwarp();
                int sel2 = s_sel;
                kk = s_kk;
                int nextcnt = (int)(h128[sel2] - ((sel2 < 127) ? h128[sel2 + 1] : 0u));
                bool fits = nextcnt <= CAP;
                // sum of fully-included sub-bins
#pragma unroll
                for (int j = 0; j < 4; j++) {
                    int idx = lane + 32 * j;
                    if (idx > sel2) lacc += (double)s128f[idx];
                }
                if (shift > 0) {
                    if (!ovf) {
                        for (int i = lane; i < curn; i += 32) {
                            float v2 = cur[i];
                            if (((__float_as_uint(v2) >> shift) & 127u) == (unsigned)sel2)
                                nxt[atomicAdd(&s_n, 1)] = v2;
                        }
                    } else if (fits) {
                        const float* negp = g_neg + b * NA;
                        for (int i = lane; i < NA; i += 32) {
                            float v2 = negp[i];
                            unsigned bits = __float_as_uint(v2);
                            if ((bits >> (shift + 7)) == pref &&
                                ((bits >> shift) & 127u) == (unsigned)sel2)
                                cur[atomicAdd(&s_n, 1)] = v2;
                        }
                    }
                    __syncwarp();
                    if (!ovf) {
                        curn = s_n;
                        float* t = cur; cur = nxt; nxt = t;
                    } else if (fits) {
                        ovf = false;
                        curn = s_n;
                    }
                }
                pref = (pref << 7) | (unsigned)sel2;
                __syncwarp();
            }
            // warp reduce lacc
#pragma unroll
            for (int o = 16; o; o >>= 1) lacc += __shfl_down_sync(0xffffffffu, lacc, o);
            if (lane == 0)
                s_acc += lacc + (double)kk * (double)__uint_as_float(pref);
        }
        __syncthreads();
        negacc = s_acc;
    }

    if (tid == 0) {
        g_cf[b]   = (kn > 0) ? posn + (float)(negacc / (double)kn) : posn;
        g_locf[b] = locim;
        g_npf[b]  = np;
        __threadfence();
        unsigned t = atomicAdd(&g_done, 1u);
        if (t == B - 1) {
            g_done = 0;
            __threadfence();
            float cs = 0.f, ls = 0.f; int ns = 0;
#pragma unroll
            for (int i = 0; i < B; i++) {
                cs += __ldcg(&g_cf[i]);
                ls += __ldcg(&g_locf[i]);
                ns += __ldcg(&g_npf[i]);
            }
            out[0] = ls / (float)max(ns, 1) + cs / (float)B;
        }
    }
}

// ---------------- entry ----------------
extern "C" void kernel_launch(void* const* d_in, const int* in_sizes, int n_in,
                              void* d_out, int out_size) {
    const float4* bbox    = (const float4*)d_in[0];
    const float*  conf    = (const float*)d_in[1];
    const float4* anchors = (const float4*)d_in[2];
    const float4* gt      = (const float4*)d_in[3];

    cudaFuncSetAttribute(k_tail, cudaFuncAttributeMaxDynamicSharedMemorySize,
                         2 * CAP * (int)sizeof(float));

    k_main<<<B * IOU_BLKS, 256>>>(bbox, conf, anchors, gt);
    k_tail<<<B, 1024, 2 * CAP * sizeof(float)>>>(bbox, conf, anchors, gt, (float*)d_out);
}

// round 8
// speedup vs baseline: 1.5137x; 1.5137x over previous
#include <cuda_runtime.h>

#define B 16
#define NA 65536
#define NG 32
#define IOU_BLKS 64      // per image: 64 blocks x 256 threads x 4 anchors
#define SCAN_BLKS 16

// ---------------- scratch (device globals; zero at module load) ----------------
__device__ unsigned long long g_spart[B * IOU_BLKS * NG];
__device__ float        g_neg[B * NA];
__device__ unsigned int g_hcnt[B * 2048];   // k_main atomics; k_corr consumes + re-zeroes
__device__ int   g_np[B];
__device__ float g_loc[B];
__device__ float g_pos[B];
// k_corr outputs
__device__ int      g_sel[B];     // coarse boundary bin (may be -1 = sum everything)
__device__ unsigned g_kkv[B];     // remaining count in boundary bin (0 = none)
__device__ float    g_posn[B];
__device__ int      g_knv[B];
// k_scan state
__device__ double       g_part[B * SCAN_BLKS];
__device__ unsigned int g_scnt[B * 1024];   // sub-hist counts (finalize re-zeroes)
__device__ float        g_ssum[B * 1024];   // sub-hist sums
__device__ unsigned int g_tick[B];
// finals
__device__ float g_cf[B];
__device__ float g_locf[B];
__device__ int   g_npf[B];
__device__ unsigned g_done;

__device__ __forceinline__ float sl1(float x) {
    float ax = fabsf(x);
    return ax < 1.f ? 0.5f * ax * ax : ax - 0.5f;
}

// ---------------- K1: IoU + per-anchor loss + count hist (unchanged) ----------------
__global__ __launch_bounds__(256) void k_main(const float4* __restrict__ bbox,
                                              const float* __restrict__ conf,
                                              const float4* __restrict__ anchors,
                                              const float4* __restrict__ gt) {
    __shared__ float4 sgt[NG];
    __shared__ float sarea[NG];
    __shared__ unsigned long long sp[8][NG];
    __shared__ unsigned int shist[2048];
    __shared__ int s_np; __shared__ float s_loc, s_pos;

    int tid = threadIdx.x, lane = tid & 31, wid = tid >> 5;
    int b = blockIdx.x >> 6, blk = blockIdx.x & 63;
    int abase = blk * 1024 + tid * 4;

    for (int i = tid; i < 2048; i += 256) shist[i] = 0;
    if (tid < NG) {
        float4 g = gt[b * NG + tid];
        sgt[tid] = g;
        sarea[tid] = (g.z - g.x) * (g.w - g.y);
    }
    if (tid == 0) { s_np = 0; s_loc = 0.f; s_pos = 0.f; }
    __syncthreads();

    float4 an[4]; float ar[4], best[4]; int bg[4];
    const float4* ap = anchors + b * NA + abase;
#pragma unroll
    for (int j = 0; j < 4; j++) {
        an[j] = ap[j];
        ar[j] = (an[j].z - an[j].x) * (an[j].w - an[j].y);
        best[j] = -1.f; bg[j] = 0;
    }

#pragma unroll 2
    for (int g = 0; g < NG; g++) {
        float4 gb = sgt[g];
        float sa = sarea[g];
        float gmax = -1.f; int gidx = 0;
#pragma unroll
        for (int j = 0; j < 4; j++) {
            float lx = fmaxf(an[j].x, gb.x), ly = fmaxf(an[j].y, gb.y);
            float rx = fminf(an[j].z, gb.z), ry = fminf(an[j].w, gb.w);
            float w = fmaxf(rx - lx, 0.f), h = fmaxf(ry - ly, 0.f);
            float inter = w * h;
            float q = __fdividef(inter, (ar[j] + sa) - inter);
            if (q > best[j]) { best[j] = q; bg[j] = g; }   // first max = lowest g
            if (q > gmax) { gmax = q; gidx = j; }          // first max = lowest anchor
        }
        unsigned bits = __float_as_uint(gmax);
        unsigned m = __reduce_max_sync(0xffffffffu, bits);
        unsigned ball = __ballot_sync(0xffffffffu, bits == m);
        if (lane == (__ffs(ball) - 1))
            sp[wid][g] = ((unsigned long long)m << 32) | (unsigned)(~(abase + gidx));
    }

    float4 cf4 = *(const float4*)(conf + b * NA + abase);
    float pv[4] = {cf4.x, cf4.y, cf4.z, cf4.w};
    float ng[4];
    int npl = 0; float locl = 0.f, posl = 0.f;
#pragma unroll
    for (int j = 0; j < 4; j++) {
        if (best[j] > 0.5f) {
            ng[j] = 0.f;
            posl += -__logf(pv[j]);
            float4 bp = bbox[b * NA + abase + j];
            float4 m = sgt[bg[j]];
            float d0 = (bp.x + bp.z) * 0.5f - (m.x + m.z) * 0.5f;
            float d1 = (bp.y + bp.w) * 0.5f - (m.y + m.w) * 0.5f;
            float d2 = (bp.z - bp.x) - (m.z - m.x);
            float d3 = (bp.w - bp.y) - (m.w - m.y);
            locl += sl1(d0) + sl1(d1) + sl1(d2) + sl1(d3);
            npl++;
        } else {
            ng[j] = fmaxf(-__logf(1.0f - pv[j]), 0.0f);
        }
        atomicAdd(&shist[__float_as_uint(ng[j]) >> 21], 1u);
    }
    *(float4*)(g_neg + b * NA + abase) = make_float4(ng[0], ng[1], ng[2], ng[3]);
    if (npl) { atomicAdd(&s_np, npl); atomicAdd(&s_loc, locl); atomicAdd(&s_pos, posl); }
    __syncthreads();

    for (int i = tid; i < 2048; i += 256) {
        unsigned c = shist[i];
        if (c) atomicAdd(&g_hcnt[b * 2048 + i], c);
    }
    if (tid < NG) {
        unsigned long long m = sp[0][tid];
#pragma unroll
        for (int w = 1; w < 8; w++) { unsigned long long v = sp[w][tid]; if (v > m) m = v; }
        g_spart[(b * IOU_BLKS + blk) * NG + tid] = m;
    }
    if (tid == 0 && s_np) {
        atomicAdd(&g_np[b], s_np);
        atomicAdd(&g_loc[b], s_loc);
        atomicAdd(&g_pos[b], s_pos);
    }
}

// ---------------- K2: corrections + coarse bin select ----------------
__global__ __launch_bounds__(1024) void k_corr(const float4* __restrict__ bbox,
                                               const float* __restrict__ conf,
                                               const float4* __restrict__ anchors,
                                               const float4* __restrict__ gt) {
    __shared__ float4 sgt[NG];
    __shared__ float sarea[NG];
    __shared__ unsigned scnt[2048];
    __shared__ unsigned long long s_gmax[NG];
    __shared__ int s_af[NG];
    __shared__ int s_npc; __shared__ float s_locc, s_posc;
    __shared__ int s_sel; __shared__ unsigned s_kk, s_cnt;

    int b = blockIdx.x, tid = threadIdx.x;
    int lane = tid & 31, wrp = tid >> 5;

    if (tid < NG) {
        float4 g = gt[b * NG + tid];
        sgt[tid] = g;
        sarea[tid] = (g.z - g.x) * (g.w - g.y);
        s_gmax[tid] = 0ull;
    }
    if (tid == 0) { s_npc = 0; s_locc = 0.f; s_posc = 0.f; s_sel = 0; s_kk = 1; s_cnt = 0; }
    scnt[tid]        = g_hcnt[b * 2048 + tid];
    scnt[tid + 1024] = g_hcnt[b * 2048 + tid + 1024];
    g_hcnt[b * 2048 + tid] = 0;
    g_hcnt[b * 2048 + tid + 1024] = 0;
    __syncthreads();

    {
        unsigned long long v0 = g_spart[(size_t)b * 2048 + tid];
        unsigned long long v1 = g_spart[(size_t)b * 2048 + tid + 1024];
        atomicMax(&s_gmax[tid & 31], v0);
        atomicMax(&s_gmax[(tid + 1024) & 31], v1);
    }
    __syncthreads();
    if (tid < NG) s_af[tid] = (int)(~(unsigned)(s_gmax[tid] & 0xffffffffull));
    __syncthreads();

    {   // warp wrp handles forced anchor of gt wrp
        int af = s_af[wrp];
        unsigned dup = __ballot_sync(0xffffffffu, lane < wrp && s_af[lane] == af);
        if (dup == 0) {
            float4 an = anchors[b * NA + af];
            float area_a = (an.z - an.x) * (an.w - an.y);
            float4 gb = sgt[lane];
            float lx = fmaxf(an.x, gb.x), ly = fmaxf(an.y, gb.y);
            float rx = fminf(an.z, gb.z), ry = fminf(an.w, gb.w);
            float w = fmaxf(rx - lx, 0.f), h = fmaxf(ry - ly, 0.f);
            float inter = w * h;
            float q = __fdividef(inter, (area_a + sarea[lane]) - inter);  // bit-identical to K1
            unsigned bits = __float_as_uint(q);
            unsigned m = __reduce_max_sync(0xffffffffu, bits);
            unsigned ball = __ballot_sync(0xffffffffu, bits == m);
            int bgi = __ffs(ball) - 1;
            float bestq = __uint_as_float(m);
            if (!(bestq > 0.5f) && lane == 0) {
                int idx = b * NA + af;
                float old = g_neg[idx];
                g_neg[idx] = 0.f;
                atomicSub(&scnt[__float_as_uint(old) >> 21], 1u);
                atomicAdd(&scnt[0], 1u);
                float p = conf[idx];
                float4 bp = bbox[idx];
                float4 mg = sgt[bgi];
                float d0 = (bp.x + bp.z) * 0.5f - (mg.x + mg.z) * 0.5f;
                float d1 = (bp.y + bp.w) * 0.5f - (mg.y + mg.w) * 0.5f;
                float d2 = (bp.z - bp.x) - (mg.z - mg.x);
                float d3 = (bp.w - bp.y) - (mg.w - mg.y);
                atomicAdd(&s_npc, 1);
                atomicAdd(&s_locc, sl1(d0) + sl1(d1) + sl1(d2) + sl1(d3));
                atomicAdd(&s_posc, -__logf(p));
            }
        }
    }
    __syncthreads();

    int np = g_np[b] + s_npc;
    float posn = (g_pos[b] + s_posc) / (float)max(np, 1);
    float locim = g_loc[b] + s_locc;
    int kn = min(3 * np, NA - np);

    // suffix-inclusive scan of 2048 counts
    for (int off = 1; off < 2048; off <<= 1) {
        unsigned a0 = (tid + off < 2048) ? scnt[tid + off] : 0u;
        unsigned a1 = (tid + 1024 + off < 2048) ? scnt[tid + 1024 + off] : 0u;
        __syncthreads();
        scnt[tid] += a0; scnt[tid + 1024] += a1;
        __syncthreads();
    }
    unsigned kk0 = (unsigned)max(kn, 1);
    {
        unsigned incl0 = scnt[tid], excl0 = scnt[tid + 1];
        if (excl0 < kk0 && kk0 <= incl0) { s_sel = tid; s_kk = kk0 - excl0; s_cnt = incl0 - excl0; }
        int i1 = tid + 1024;
        unsigned incl1 = scnt[i1], excl1 = (i1 < 2047) ? scnt[i1 + 1] : 0u;
        if (excl1 < kk0 && kk0 <= incl1) { s_sel = i1; s_kk = kk0 - excl1; s_cnt = incl1 - excl1; }
    }
    __syncthreads();

    if (tid == 0) {
        g_np[b] = 0; g_loc[b] = 0.f; g_pos[b] = 0.f;   // clean for next replay
        g_posn[b] = posn;
        g_locf[b] = locim;
        g_npf[b]  = np;
        g_knv[b]  = kn;
        if (kn <= 0) {
            g_cf[b] = posn;                // finalize leaves it
        } else {
            int selo = s_sel; unsigned kko = s_kk;
            if (kko == s_cnt) { selo -= 1; kko = 0; }   // boundary bin fully taken
            g_sel[b] = selo;
            g_kkv[b] = kko;
        }
    }
}

// ---------------- K3: parallel scan + per-image finalize + global finalize ----------------
__global__ __launch_bounds__(256) void k_scan(float* __restrict__ out) {
    __shared__ double sred8[8];
    __shared__ unsigned sc[1024];
    __shared__ int s_last, s_sub;
    __shared__ unsigned s_kk2;

    int blk = blockIdx.x;
    int b = blk >> 4, seg = blk & 15;
    int tid = threadIdx.x;
    int lane = tid & 31;

    int kn = g_knv[b];
    int sel = (kn > 0) ? g_sel[b] : 0x7fffffff;   // sentinel: no sums
    unsigned kk = (kn > 0) ? g_kkv[b] : 0u;
    float posn = g_posn[b];

    // ---- phase 1: scan this block's 4096 elements ----
    float acc = 0.f;
    if (kn > 0) {
        const float4* p4 = (const float4*)(g_neg + b * NA) + seg * 1024;
#pragma unroll
        for (int ii = 0; ii < 4; ii++) {
            float4 v = p4[tid + ii * 256];
            float vv[4] = {v.x, v.y, v.z, v.w};
#pragma unroll
            for (int c = 0; c < 4; c++) {
                unsigned bits = __float_as_uint(vv[c]);
                int key = (int)(bits >> 21);
                if (key > sel) acc += vv[c];
                else if (kk && key == sel) {
                    unsigned sub = (bits >> 11) & 1023u;
                    atomicAdd(&g_scnt[b * 1024 + sub], 1u);
                    atomicAdd(&g_ssum[b * 1024 + sub], vv[c]);
                }
            }
        }
    }
    // block reduce partial (double)
    double d = (double)acc;
#pragma unroll
    for (int o = 16; o; o >>= 1) d += __shfl_down_sync(0xffffffffu, d, o);
    if (lane == 0) sred8[tid >> 5] = d;
    __syncthreads();
    if (tid == 0) {
        double t = 0.0;
#pragma unroll
        for (int w = 0; w < 8; w++) t += sred8[w];
        g_part[b * SCAN_BLKS + seg] = t;
        __threadfence();
        unsigned t2 = atomicAdd(&g_tick[b], 1u);
        s_last = (t2 == SCAN_BLKS - 1);
    }
    __syncthreads();
    if (!s_last) return;

    // ---- phase 2 (one block per image): finalize ----
    __threadfence();
    double dacc = (tid < SCAN_BLKS) ? __ldcg(&g_part[b * SCAN_BLKS + tid]) : 0.0;
    unsigned kk2 = 0;
    float T = 0.f;

    if (kn > 0) {
        unsigned c4[4]; float f4[4];
#pragma unroll
        for (int j = 0; j < 4; j++) {
            int idx = tid + 256 * j;
            c4[j] = __ldcg(&g_scnt[b * 1024 + idx]);
            f4[j] = __ldcg(&g_ssum[b * 1024 + idx]);
            g_scnt[b * 1024 + idx] = 0u;            // clean for next replay
            g_ssum[b * 1024 + idx] = 0.f;
        }
        if (kk > 0) {
#pragma unroll
            for (int j = 0; j < 4; j++) sc[tid + 256 * j] = c4[j];
            if (tid == 0) { s_sub = 0; s_kk2 = 0; }
            __syncthreads();
            // suffix-inclusive scan of 1024 sub-bins
            for (int off = 1; off < 1024; off <<= 1) {
                unsigned a[4];
#pragma unroll
                for (int j = 0; j < 4; j++) {
                    int idx = tid + 256 * j;
                    a[j] = (idx + off < 1024) ? sc[idx + off] : 0u;
                }
                __syncthreads();
#pragma unroll
                for (int j = 0; j < 4; j++) sc[tid + 256 * j] += a[j];
                __syncthreads();
            }
#pragma unroll
            for (int j = 0; j < 4; j++) {
                int idx = tid + 256 * j;
                unsigned incl = sc[idx], excl = (idx < 1023) ? sc[idx + 1] : 0u;
                if (excl < kk && kk <= incl) { s_sub = idx; s_kk2 = kk - excl; }
            }
            __syncthreads();
            int sub = s_sub;
            kk2 = s_kk2;
#pragma unroll
            for (int j = 0; j < 4; j++) {
                int idx = tid + 256 * j;
                if (idx > sub) dacc += (double)f4[j];
            }
            T = __uint_as_float(((unsigned)sel << 21) | ((unsigned)sub << 11));
        }
        // block reduce dacc
#pragma unroll
        for (int o = 16; o; o >>= 1) dacc += __shfl_down_sync(0xffffffffu, dacc, o);
        if (lane == 0) sred8[tid >> 5] = dacc;
        __syncthreads();
        if (tid == 0) {
            double tot = 0.0;
#pragma unroll
            for (int w = 0; w < 8; w++) tot += sred8[w];
            double negloss = tot + (double)kk2 * (double)T;
            g_cf[b] = posn + (float)(negloss / (double)kn);
        }
    }

    if (tid == 0) {
        g_tick[b] = 0;                               // clean for next replay
        __threadfence();
        unsigned t = atomicAdd(&g_done, 1u);
        if (t == B - 1) {
            g_done = 0;
            __threadfence();
            float cs = 0.f, ls = 0.f; int ns = 0;
#pragma unroll
            for (int i = 0; i < B; i++) {
                cs += __ldcg(&g_cf[i]);
                ls += __ldcg(&g_locf[i]);
                ns += __ldcg(&g_npf[i]);
            }
            out[0] = ls / (float)max(ns, 1) + cs / (float)B;
        }
    }
}

// ---------------- entry ----------------
extern "C" void kernel_launch(void* const* d_in, const int* in_sizes, int n_in,
                              void* d_out, int out_size) {
    const float4* bbox    = (const float4*)d_in[0];
    const float*  conf    = (const float*)d_in[1];
    const float4* anchors = (const float4*)d_in[2];
    const float4* gt      = (const float4*)d_in[3];

    k_main<<<B * IOU_BLKS, 256>>>(bbox, conf, anchors, gt);
    k_corr<<<B, 1024>>>(bbox, conf, anchors, gt);
    k_scan<<<B * SCAN_BLKS, 256>>>((float*)d_out);
}